// round 15
// baseline (speedup 1.0000x reference)
#include <cuda_runtime.h>
#include <cuda_bf16.h>
#include <math.h>
#include <stdint.h>

#define NN 100000
#define EE 1200000
#define CC 64
#define HH 64
#define OUTC 10
#define GG 128
#define LL 3
#define EPSBN 1e-5f

// ---------------- scratch (device globals) ----------------
__device__ float    g_h [NN * HH];    // scaled features  hhat = dis * h
__device__ uint32_t g_awh[NN * 32];   // agg output, bf16x2 hi
__device__ uint32_t g_awl[NN * 32];   // agg output, bf16x2 lo
__device__ int   g_outdeg[NN];
__device__ int   g_indeg [NN];
__device__ int   g_rowptr[NN + 1];
__device__ int   g_cur   [NN];
__device__ int   g_col   [EE];
__device__ float g_dis   [NN];
__device__ float g_sumdis[NN];
__device__ int   g_bsum  [128];
__device__ int   g_boff  [128];
__device__ float g_stat_s[4 * 64];
__device__ float g_stat_q[4 * 64];
__device__ float g_hg    [GG * HH];
__device__ uint32_t g_Bhi[4 * 2048];
__device__ uint32_t g_Blo[4 * 2048];

static __device__ __forceinline__ void split2(float x, float y, uint32_t& hi, uint32_t& lo) {
    __nv_bfloat16 hx = __float2bfloat16(x), hy = __float2bfloat16(y);
    __nv_bfloat16 lx = __float2bfloat16(x - __bfloat162float(hx));
    __nv_bfloat16 ly = __float2bfloat16(y - __bfloat162float(hy));
    hi = (uint32_t)__bfloat16_as_ushort(hx) | ((uint32_t)__bfloat16_as_ushort(hy) << 16);
    lo = (uint32_t)__bfloat16_as_ushort(lx) | ((uint32_t)__bfloat16_as_ushort(ly) << 16);
}

#define MMA_BF16(c, a0, a1, a2, a3, b0, b1) \
    asm volatile("mma.sync.aligned.m16n8k16.row.col.f32.bf16.bf16.f32 " \
        "{%0,%1,%2,%3}, {%4,%5,%6,%7}, {%8,%9}, {%0,%1,%2,%3};" \
        : "+f"(c[0]), "+f"(c[1]), "+f"(c[2]), "+f"(c[3]) \
        : "r"(a0), "r"(a1), "r"(a2), "r"(a3), "r"(b0), "r"(b1))

// ---------------- CSR chain ----------------
__global__ void k_zero_deg() {
    int i = blockIdx.x * blockDim.x + threadIdx.x;
    if (i < NN) { g_outdeg[i] = 0; g_indeg[i] = 0; g_sumdis[i] = 0.f; }
}

__global__ void k_hist(const int* __restrict__ src, const int* __restrict__ dst) {
    int e = blockIdx.x * blockDim.x + threadIdx.x;
    if (e < EE) {
        atomicAdd(&g_indeg[dst[e]], 1);
        atomicAdd(&g_outdeg[src[e]], 1);
    }
}

// shuffle-based block scan (1024 threads, 2 barriers)
__global__ void k_scan1() {
    __shared__ int wtot[32];
    int t = threadIdx.x, lane = t & 31, w = t >> 5;
    int i = blockIdx.x * 1024 + t;
    int v = (i < NN) ? g_indeg[i] : 0;
    int x = v;
    #pragma unroll
    for (int o = 1; o < 32; o <<= 1) {
        int y = __shfl_up_sync(0xFFFFFFFFu, x, o);
        if (lane >= o) x += y;
    }
    if (lane == 31) wtot[w] = x;
    __syncthreads();
    if (w == 0) {
        int y = wtot[lane];
        #pragma unroll
        for (int o = 1; o < 32; o <<= 1) {
            int z = __shfl_up_sync(0xFFFFFFFFu, y, o);
            if (lane >= o) y += z;
        }
        wtot[lane] = y;
    }
    __syncthreads();
    int excl = x - v + (w > 0 ? wtot[w - 1] : 0);
    if (i < NN) g_rowptr[i] = excl;
    if (t == 1023) g_bsum[blockIdx.x] = wtot[31];
}

__global__ void k_scan2(int nb) {
    __shared__ int wtot[4];
    int t = threadIdx.x, lane = t & 31, w = t >> 5;
    int v = (t < nb) ? g_bsum[t] : 0;
    int x = v;
    #pragma unroll
    for (int o = 1; o < 32; o <<= 1) {
        int y = __shfl_up_sync(0xFFFFFFFFu, x, o);
        if (lane >= o) x += y;
    }
    if (lane == 31) wtot[w] = x;
    __syncthreads();
    int off = 0;
    for (int j = 0; j < w; j++) off += wtot[j];
    g_boff[t] = x - v + off;
    if (t == 127) g_rowptr[NN] = off + x;
}

__global__ void k_scan3() {
    int i = blockIdx.x * 1024 + threadIdx.x;
    if (i < NN) {
        int v = g_rowptr[i] + g_boff[blockIdx.x];
        g_rowptr[i] = v;
        g_cur[i] = v;
        g_dis[i] = rsqrtf((float)g_outdeg[i] + 1.0f);
    }
}

__global__ void k_fill(const int* __restrict__ src, const int* __restrict__ dst) {
    int e = blockIdx.x * blockDim.x + threadIdx.x;
    if (e < EE) {
        int s = src[e];
        int d = dst[e];
        int p = atomicAdd(&g_cur[d], 1);
        g_col[p] = s;
        atomicAdd(&g_sumdis[d], g_dis[s]);
    }
}

// ---------------- feature chain setup ----------------
__global__ void k_prep(const float* __restrict__ Wf, const float* __restrict__ Wc) {
    int t = blockIdx.x * blockDim.x + threadIdx.x;
    if (t < 256) { g_stat_s[t] = 0.f; g_stat_q[t] = 0.f; }
    if (t < GG * HH) g_hg[t] = 0.f;
    if (t < 8192) {
        int L = t >> 11, rem = t & 2047;
        int n = rem >> 5, kp = rem & 31;
        const float* W = (L == 0) ? Wf : (Wc + (L - 1) * 4096);
        float w0 = W[(2 * kp) * 64 + n];
        float w1 = W[(2 * kp + 1) * 64 + n];
        uint32_t hi, lo;
        split2(w0, w1, hi, lo);
        g_Bhi[L * 2048 + rem] = hi;
        g_Blo[L * 2048 + rem] = lo;
    }
}

__global__ void k_colstats(const float* __restrict__ A) {
    __shared__ float rs[256], rq[256];
    int c  = threadIdx.x & 63;
    int rr = threadIdx.x >> 6;
    int rbeg = blockIdx.x * 512;
    int rend = rbeg + 512; if (rend > NN) rend = NN;
    float s = 0.f, q = 0.f;
    for (int r = rbeg + rr; r < rend; r += 4) {
        float v = A[(size_t)r * 64 + c];
        s += v; q += v * v;
    }
    rs[threadIdx.x] = s; rq[threadIdx.x] = q;
    __syncthreads();
    if (threadIdx.x < 64) {
        float S = rs[threadIdx.x] + rs[threadIdx.x + 64] + rs[threadIdx.x + 128] + rs[threadIdx.x + 192];
        float Q = rq[threadIdx.x] + rq[threadIdx.x + 64] + rq[threadIdx.x + 128] + rq[threadIdx.x + 192];
        atomicAdd(&g_stat_s[threadIdx.x], S);
        atomicAdd(&g_stat_q[threadIdx.x], Q);
    }
}

// ---------------- mma.sync GEMM: 128 threads, warp covers 32 rows x 64 cols ----------------
// smem: s_s[0,256) s_t[256,512) BH[512,9728) BL[9728,18944) AH[18944,37376) AL[37376,55808)
// epilogue reuse: T @512 (128x66 f32 -> 33792B, ends 34304), rS @34304, rQ @34816, sbatch @35328
__global__ __launch_bounds__(128)
void k_gemm_mma(const float* __restrict__ A, int layer,
                const float* __restrict__ bias, float* __restrict__ out,
                int statSlot, int foldSlot, int poolMode, int aBf16,
                const int* __restrict__ batch,
                const float* __restrict__ gam, const float* __restrict__ bet) {
    extern __shared__ __align__(16) char sm[];
    float*    s_s = (float*)sm;
    float*    s_t = (float*)(sm + 256);
    uint32_t* BH  = (uint32_t*)(sm + 512);
    uint32_t* BL  = (uint32_t*)(sm + 9728);
    uint32_t* AH  = (uint32_t*)(sm + 18944);
    uint32_t* AL  = (uint32_t*)(sm + 37376);
    int tid = threadIdx.x;
    int rowBase = blockIdx.x * 128;
    int lane = tid & 31, wr = tid >> 5;

    if (foldSlot >= 0 && tid < 64) {
        float invn = 1.0f / (float)NN;
        float mu  = g_stat_s[foldSlot * 64 + tid] * invn;
        float var = fmaxf(g_stat_q[foldSlot * 64 + tid] * invn - mu * mu, 0.f);
        float sc = rsqrtf(var + EPSBN) * gam[tid];
        s_s[tid] = sc;
        s_t[tid] = bet[tid] - mu * sc;
    }

    // stage B (stride 36 words per n-row)
    {
        const uint32_t* gBH = g_Bhi + layer * 2048;
        const uint32_t* gBL = g_Blo + layer * 2048;
        for (int i = tid; i < 2048; i += 128) {
            int n = i >> 5, kp = i & 31;
            BH[n * 36 + kp] = gBH[i];
            BL[n * 36 + kp] = gBL[i];
        }
    }
    __syncthreads();

    // stage A: thread = full row
    {
        int row = tid;
        int grow = rowBase + row;
        bool valid = grow < NN;
        uint32_t base = row * 36;
        if (aBf16) {
            if (valid) {
                const uint4* ph4 = (const uint4*)(g_awh + (size_t)grow * 32);
                const uint4* pl4 = (const uint4*)(g_awl + (size_t)grow * 32);
                #pragma unroll
                for (int j = 0; j < 8; j++) {
                    *(uint4*)(AH + base + 4 * j) = ph4[j];
                    *(uint4*)(AL + base + 4 * j) = pl4[j];
                }
            } else {
                #pragma unroll
                for (int j = 0; j < 8; j++) {
                    *(uint4*)(AH + base + 4 * j) = make_uint4(0, 0, 0, 0);
                    *(uint4*)(AL + base + 4 * j) = make_uint4(0, 0, 0, 0);
                }
            }
        } else {
            const float4* ap = (const float4*)(A + (size_t)grow * 64);
            bool dofold = (foldSlot >= 0);
            #pragma unroll
            for (int j = 0; j < 8; j++) {   // 8 float4 pairs -> process 2 float4 per j? do 16 quads
                ;
            }
            uint32_t hb[32], lb[32];
            #pragma unroll
            for (int j = 0; j < 16; j++) {
                float4 v = valid ? ap[j] : make_float4(0.f, 0.f, 0.f, 0.f);
                if (dofold) {
                    int c0 = j * 4;
                    v.x = v.x * s_s[c0]     + s_t[c0];
                    v.y = v.y * s_s[c0 + 1] + s_t[c0 + 1];
                    v.z = v.z * s_s[c0 + 2] + s_t[c0 + 2];
                    v.w = v.w * s_s[c0 + 3] + s_t[c0 + 3];
                }
                split2(v.x, v.y, hb[2 * j],     lb[2 * j]);
                split2(v.z, v.w, hb[2 * j + 1], lb[2 * j + 1]);
            }
            #pragma unroll
            for (int j = 0; j < 8; j++) {
                *(uint4*)(AH + base + 4 * j) = make_uint4(hb[4 * j], hb[4 * j + 1], hb[4 * j + 2], hb[4 * j + 3]);
                *(uint4*)(AL + base + 4 * j) = make_uint4(lb[4 * j], lb[4 * j + 1], lb[4 * j + 2], lb[4 * j + 3]);
            }
        }
    }
    __syncthreads();

    // MMA: warp wr owns rows wr*32 .. wr*32+31 (two m16 row-tiles), all 64 cols
    int g = lane >> 2, t = lane & 3;
    float acc[2][8][4];
    #pragma unroll
    for (int tt = 0; tt < 2; tt++)
        #pragma unroll
        for (int nf = 0; nf < 8; nf++)
            #pragma unroll
            for (int j = 0; j < 4; j++) acc[tt][nf][j] = 0.f;

    int arA = (wr * 32 + g) * 36;        // tile0 rows g, g+8
    int arB = (wr * 32 + g + 8) * 36;
    int arC = (wr * 32 + g + 16) * 36;   // tile1 rows g+16, g+24
    int arD = (wr * 32 + g + 24) * 36;
    #pragma unroll
    for (int kc = 0; kc < 4; kc++) {
        int kb = kc * 8 + t;
        uint32_t ah0 = AH[arA + kb],     ah1 = AH[arB + kb];
        uint32_t ah2 = AH[arA + kb + 4], ah3 = AH[arB + kb + 4];
        uint32_t al0 = AL[arA + kb],     al1 = AL[arB + kb];
        uint32_t al2 = AL[arA + kb + 4], al3 = AL[arB + kb + 4];
        uint32_t ch0 = AH[arC + kb],     ch1 = AH[arD + kb];
        uint32_t ch2 = AH[arC + kb + 4], ch3 = AH[arD + kb + 4];
        uint32_t cl0 = AL[arC + kb],     cl1 = AL[arD + kb];
        uint32_t cl2 = AL[arC + kb + 4], cl3 = AL[arD + kb + 4];
        #pragma unroll
        for (int nf = 0; nf < 8; nf++) {
            int nb = (nf * 8 + g) * 36 + kb;
            uint32_t bh0 = BH[nb], bh1 = BH[nb + 4];
            uint32_t bl0 = BL[nb], bl1 = BL[nb + 4];
            MMA_BF16(acc[0][nf], ah0, ah1, ah2, ah3, bh0, bh1);
            MMA_BF16(acc[0][nf], ah0, ah1, ah2, ah3, bl0, bl1);
            MMA_BF16(acc[0][nf], al0, al1, al2, al3, bh0, bh1);
            MMA_BF16(acc[1][nf], ch0, ch1, ch2, ch3, bh0, bh1);
            MMA_BF16(acc[1][nf], ch0, ch1, ch2, ch3, bl0, bl1);
            MMA_BF16(acc[1][nf], cl0, cl1, cl2, cl3, bh0, bh1);
        }
    }
    __syncthreads();   // A/B tiles dead; T may overwrite

    int* sbatch = (int*)(sm + 35328);
    if (poolMode) {
        int grow = rowBase + tid;
        sbatch[tid] = batch[grow < NN ? grow : NN - 1];
    }

    // epilogue
    {
        float* T = (float*)(sm + 512);
        bool needT = (statSlot >= 0) || poolMode;
        #pragma unroll
        for (int tt = 0; tt < 2; tt++) {
            int lr0 = wr * 32 + tt * 16 + g;
            int r0 = rowBase + lr0, r1 = r0 + 8;
            bool v0 = r0 < NN, v1 = r1 < NN;
            float d0 = 1.f, d1 = 1.f;
            if (!poolMode) {
                if (v0) d0 = g_dis[r0];
                if (v1) d1 = g_dis[r1];
            }
            #pragma unroll
            for (int nf = 0; nf < 8; nf++) {
                int col = nf * 8 + 2 * t;
                float2 bb = *(const float2*)(bias + col);
                float2 o0, o1;
                o0.x = fmaxf(acc[tt][nf][0] + bb.x, 0.f);
                o0.y = fmaxf(acc[tt][nf][1] + bb.y, 0.f);
                o1.x = fmaxf(acc[tt][nf][2] + bb.x, 0.f);
                o1.y = fmaxf(acc[tt][nf][3] + bb.y, 0.f);
                if (!poolMode) {
                    if (v0) *(float2*)(out + (size_t)r0 * 64 + col) = make_float2(o0.x * d0, o0.y * d0);
                    if (v1) *(float2*)(out + (size_t)r1 * 64 + col) = make_float2(o1.x * d1, o1.y * d1);
                }
                if (needT) {
                    if (!v0) { o0.x = 0.f; o0.y = 0.f; }
                    if (!v1) { o1.x = 0.f; o1.y = 0.f; }
                    *(float2*)(T + lr0 * 66 + col)       = o0;
                    *(float2*)(T + (lr0 + 8) * 66 + col) = o1;
                }
            }
        }
    }
    if (statSlot >= 0) {
        __syncthreads();
        float* T  = (float*)(sm + 512);
        float* rS = (float*)(sm + 34304);
        float* rQ = (float*)(sm + 34816);
        int c = tid & 63, q = tid >> 6;     // q in {0,1}
        float S = 0.f, Q = 0.f;
        for (int r = q * 64; r < q * 64 + 64; r++) {
            float v = T[r * 66 + c];
            S += v; Q += v * v;
        }
        rS[tid] = S; rQ[tid] = Q;
        __syncthreads();
        if (tid < 64) {
            atomicAdd(&g_stat_s[statSlot * 64 + tid], rS[tid] + rS[tid + 64]);
            atomicAdd(&g_stat_q[statSlot * 64 + tid], rQ[tid] + rQ[tid + 64]);
        }
    }
    if (poolMode) {
        __syncthreads();
        float* T = (float*)(sm + 512);
        int c = tid & 63, q = tid >> 6;
        int r0 = q * 64;
        int cur = sbatch[r0];
        float s = 0.f;
        for (int r = 0; r < 64; r++) {
            int gid = sbatch[r0 + r];
            if (gid != cur) {
                atomicAdd(&g_hg[cur * 64 + c], s);
                s = 0.f; cur = gid;
            }
            s += T[(r0 + r) * 66 + c];
        }
        atomicAdd(&g_hg[cur * 64 + c], s);
    }
}

// ---------------- aggregation (warp per node; pre-scaled inputs; bf16-split output) ----------------
__global__ __launch_bounds__(256)
void k_agg(const float* __restrict__ Ain,
           int slot, const float* __restrict__ gam, const float* __restrict__ bet) {
    __shared__ float s_sc[64], s_sh[64];
    if (threadIdx.x < 64) {
        float invn = 1.0f / (float)NN;
        float mu  = g_stat_s[slot * 64 + threadIdx.x] * invn;
        float var = fmaxf(g_stat_q[slot * 64 + threadIdx.x] * invn - mu * mu, 0.f);
        float sc = rsqrtf(var + EPSBN) * gam[threadIdx.x];
        s_sc[threadIdx.x] = sc;
        s_sh[threadIdx.x] = bet[threadIdx.x] - mu * sc;
    }
    __syncthreads();

    int gtid = blockIdx.x * 256 + threadIdx.x;
    int i = gtid >> 5;
    int lane = gtid & 31;
    if (i >= NN) return;
    int c0 = lane * 2;
    float di = g_dis[i];
    int e = g_rowptr[i], end = g_rowptr[i + 1];
    float a0 = 0.f, a1 = 0.f;

    for (; e + 8 <= end; e += 8) {
        int s0 = g_col[e],     s1 = g_col[e + 1], s2 = g_col[e + 2], s3 = g_col[e + 3];
        int s4 = g_col[e + 4], s5 = g_col[e + 5], s6 = g_col[e + 6], s7 = g_col[e + 7];
        float2 v0 = *(const float2*)&Ain[(size_t)s0 * 64 + c0];
        float2 v1 = *(const float2*)&Ain[(size_t)s1 * 64 + c0];
        float2 v2 = *(const float2*)&Ain[(size_t)s2 * 64 + c0];
        float2 v3 = *(const float2*)&Ain[(size_t)s3 * 64 + c0];
        float2 v4 = *(const float2*)&Ain[(size_t)s4 * 64 + c0];
        float2 v5 = *(const float2*)&Ain[(size_t)s5 * 64 + c0];
        float2 v6 = *(const float2*)&Ain[(size_t)s6 * 64 + c0];
        float2 v7 = *(const float2*)&Ain[(size_t)s7 * 64 + c0];
        a0 += v0.x + v1.x + v2.x + v3.x + v4.x + v5.x + v6.x + v7.x;
        a1 += v0.y + v1.y + v2.y + v3.y + v4.y + v5.y + v6.y + v7.y;
    }
    for (; e + 4 <= end; e += 4) {
        int s0 = g_col[e], s1 = g_col[e + 1], s2 = g_col[e + 2], s3 = g_col[e + 3];
        float2 v0 = *(const float2*)&Ain[(size_t)s0 * 64 + c0];
        float2 v1 = *(const float2*)&Ain[(size_t)s1 * 64 + c0];
        float2 v2 = *(const float2*)&Ain[(size_t)s2 * 64 + c0];
        float2 v3 = *(const float2*)&Ain[(size_t)s3 * 64 + c0];
        a0 += v0.x + v1.x + v2.x + v3.x;
        a1 += v0.y + v1.y + v2.y + v3.y;
    }
    for (; e < end; e++) {
        int s = g_col[e];
        float2 v = *(const float2*)&Ain[(size_t)s * 64 + c0];
        a0 += v.x;
        a1 += v.y;
    }
    {   // self loop
        float2 v = *(const float2*)&Ain[(size_t)i * 64 + c0];
        a0 += v.x;
        a1 += v.y;
    }
    float ws = di * (g_sumdis[i] + di);
    float o0 = s_sc[c0]     * (di * a0) + ws * s_sh[c0];
    float o1 = s_sc[c0 + 1] * (di * a1) + ws * s_sh[c0 + 1];
    uint32_t hi, lo;
    split2(o0, o1, hi, lo);
    g_awh[(size_t)i * 32 + lane] = hi;
    g_awl[(size_t)i * 32 + lane] = lo;
}

// ---------------- final head ----------------
__global__ __launch_bounds__(256, 1)
void k_final(const float* __restrict__ bn1g, const float* __restrict__ bn1b,
             const float* __restrict__ Wfc,  const float* __restrict__ bfc,
             const float* __restrict__ bn2g, const float* __restrict__ bn2b,
             const float* __restrict__ Wcls, const float* __restrict__ bcls,
             float* __restrict__ out) {
    __shared__ float sA[128 * 65];
    __shared__ float red[256], red2[256];
    __shared__ float s_s[64], s_t[64];
    int tid = threadIdx.x;
    int c = tid & 63, rr = tid >> 6;

    for (int i = tid; i < 128 * 64; i += 256)
        sA[(i >> 6) * 65 + (i & 63)] = g_hg[i];
    __syncthreads();

    float s = 0.f, q = 0.f;
    for (int r = rr; r < 128; r += 4) {
        float v = sA[r * 65 + c];
        s += v; q += v * v;
    }
    red[tid] = s; red2[tid] = q;
    __syncthreads();
    if (tid < 64) {
        float S = red [tid] + red [tid + 64] + red [tid + 128] + red [tid + 192];
        float Q = red2[tid] + red2[tid + 64] + red2[tid + 128] + red2[tid + 192];
        float mu = S * (1.f / 128.f);
        float var = fmaxf(Q * (1.f / 128.f) - mu * mu, 0.f);
        float inv = rsqrtf(var + EPSBN);
        float sc = inv * bn1g[tid];
        s_s[tid] = sc;
        s_t[tid] = bn1b[tid] - mu * sc;
    }
    __syncthreads();
    for (int r = rr; r < 128; r += 4)
        sA[r * 65 + c] = sA[r * 65 + c] * s_s[c] + s_t[c];
    __syncthreads();

    float wreg[64];
    #pragma unroll
    for (int k = 0; k < 64; k++) wreg[k] = Wfc[k * 64 + c];
    float acc[32];
    for (int ri = 0; ri < 32; ri++) {
        int r = rr + ri * 4;
        float a = bfc[c];
        #pragma unroll
        for (int k = 0; k < 64; k++) a = fmaf(sA[r * 65 + k], wreg[k], a);
        acc[ri] = fmaxf(a, 0.f);
    }
    __syncthreads();
    for (int ri = 0; ri < 32; ri++) sA[(rr + ri * 4) * 65 + c] = acc[ri];
    __syncthreads();

    s = 0.f; q = 0.f;
    for (int r = rr; r < 128; r += 4) {
        float v = sA[r * 65 + c];
        s += v; q += v * v;
    }
    red[tid] = s; red2[tid] = q;
    __syncthreads();
    if (tid < 64) {
        float S = red [tid] + red [tid + 64] + red [tid + 128] + red [tid + 192];
        float Q = red2[tid] + red2[tid + 64] + red2[tid + 128] + red2[tid + 192];
        float mu = S * (1.f / 128.f);
        float var = fmaxf(Q * (1.f / 128.f) - mu * mu, 0.f);
        float inv = rsqrtf(var + EPSBN);
        float sc = inv * bn2g[tid];
        s_s[tid] = sc;
        s_t[tid] = bn2b[tid] - mu * sc;
    }
    __syncthreads();

    if (tid < 128) {
        int r = tid;
        float logits[10];
        #pragma unroll
        for (int j = 0; j < 10; j++) logits[j] = bcls[j];
        for (int k = 0; k < 64; k++) {
            float v = sA[r * 65 + k] * s_s[k] + s_t[k];
            #pragma unroll
            for (int j = 0; j < 10; j++)
                logits[j] = fmaf(v, Wcls[k * 10 + j], logits[j]);
        }
        float m = logits[0];
        #pragma unroll
        for (int j = 1; j < 10; j++) m = fmaxf(m, logits[j]);
        float se = 0.f;
        #pragma unroll
        for (int j = 0; j < 10; j++) se += expf(logits[j] - m);
        float lse = logf(se) + m;
        #pragma unroll
        for (int j = 0; j < 10; j++) out[r * 10 + j] = logits[j] - lse;
    }
}

// ---------------- host launch ----------------
extern "C" void kernel_launch(void* const* d_in, const int* in_sizes, int n_in,
                              void* d_out, int out_size) {
    const float* x         = (const float*)d_in[0];
    const int*   ei        = (const int*)  d_in[1];
    const int*   batch     = (const int*)  d_in[2];
    const float* bn_feat_g = (const float*)d_in[3];
    const float* bn_feat_b = (const float*)d_in[4];
    const float* W_feat    = (const float*)d_in[5];
    const float* b_feat    = (const float*)d_in[6];
    const float* conv_bn_g = (const float*)d_in[7];
    const float* conv_bn_b = (const float*)d_in[8];
    const float* conv_W    = (const float*)d_in[9];
    const float* conv_b    = (const float*)d_in[10];
    const float* bn_fc_g   = (const float*)d_in[11];
    const float* bn_fc_b   = (const float*)d_in[12];
    const float* W_fc      = (const float*)d_in[13];
    const float* b_fc      = (const float*)d_in[14];
    const float* bn_hid_g  = (const float*)d_in[15];
    const float* bn_hid_b  = (const float*)d_in[16];
    const float* W_cls     = (const float*)d_in[17];
    const float* b_cls     = (const float*)d_in[18];
    float* out = (float*)d_out;

    void *ph_v;
    cudaGetSymbolAddress(&ph_v, g_h);
    float* ph = (float*)ph_v;

    const int* src = ei;
    const int* dst = ei + EE;

    const int nbScan = (NN + 1023) / 1024;
    const int nbNode = (NN + 255) / 256;
    const int nbEdge = (EE + 255) / 256;
    const int nbStat = (NN + 511) / 512;
    const int nbGemm = (NN + 127) / 128;
    const int nbAgg  = (NN * 32 + 255) / 256;
    const int MMA_SMEM = 55808;

    static cudaStream_t s_csr = 0;
    static cudaEvent_t  ev_fork = 0, ev_dis = 0, ev_join = 0;
    static bool inited = false;
    if (!inited) {
        cudaStreamCreateWithFlags(&s_csr, cudaStreamNonBlocking);
        cudaEventCreateWithFlags(&ev_fork, cudaEventDisableTiming);
        cudaEventCreateWithFlags(&ev_dis,  cudaEventDisableTiming);
        cudaEventCreateWithFlags(&ev_join, cudaEventDisableTiming);
        cudaFuncSetAttribute(k_gemm_mma, cudaFuncAttributeMaxDynamicSharedMemorySize, MMA_SMEM);
        inited = true;
    }

    // ---- fork: CSR chain on s_csr, feature chain on stream 0 ----
    cudaEventRecord(ev_fork, 0);
    cudaStreamWaitEvent(s_csr, ev_fork, 0);

    k_zero_deg<<<nbNode, 256, 0, s_csr>>>();
    k_hist<<<nbEdge, 256, 0, s_csr>>>(src, dst);
    k_scan1<<<nbScan, 1024, 0, s_csr>>>();
    k_scan2<<<1, 128, 0, s_csr>>>(nbScan);
    k_scan3<<<nbScan, 1024, 0, s_csr>>>();
    cudaEventRecord(ev_dis, s_csr);
    k_fill<<<nbEdge, 256, 0, s_csr>>>(src, dst);
    cudaEventRecord(ev_join, s_csr);

    // feature chain (stream 0)
    k_prep<<<33, 256>>>(W_feat, conv_W);
    k_colstats<<<nbStat, 256>>>(x);
    cudaStreamWaitEvent(0, ev_dis, 0);
    k_gemm_mma<<<nbGemm, 128, MMA_SMEM>>>(x, 0, b_feat, ph, 1, 0, 0, 0,
                                          batch, bn_feat_g, bn_feat_b);

    // ---- join before first aggregation ----
    cudaStreamWaitEvent(0, ev_join, 0);

    // ---- conv layers ----
    for (int l = 0; l < LL; l++) {
        k_agg<<<nbAgg, 256>>>(ph, l + 1, conv_bn_g + l * HH, conv_bn_b + l * HH);
        int statSlot = (l < LL - 1) ? (l + 2) : -1;
        int poolMode = (l == LL - 1) ? 1 : 0;
        k_gemm_mma<<<nbGemm, 128, MMA_SMEM>>>((const float*)0, l + 1, conv_b + l * HH, ph,
                                              statSlot, -1, poolMode, 1,
                                              batch, (const float*)0, (const float*)0);
    }

    // ---- head ----
    k_final<<<1, 256>>>(bn_fc_g, bn_fc_b, W_fc, b_fc,
                        bn_hid_g, bn_hid_b, W_cls, b_cls, out);
}

// round 16
// speedup vs baseline: 1.1033x; 1.1033x over previous
#include <cuda_runtime.h>
#include <cuda_bf16.h>
#include <math.h>
#include <stdint.h>

#define NN 100000
#define EE 1200000
#define CC 64
#define HH 64
#define OUTC 10
#define GG 128
#define LL 3
#define EPSBN 1e-5f

// ---------------- scratch (device globals) ----------------
__device__ float    g_h [NN * HH];    // scaled features  hhat = dis * h
__device__ uint32_t g_awh[NN * 32];   // agg output, bf16x2 hi (cols 2l,2l+1 packed)
__device__ uint32_t g_awl[NN * 32];   // agg output, bf16x2 lo
__device__ int   g_outdeg[NN];
__device__ int   g_indeg [NN];
__device__ int   g_rowptr[NN + 1];
__device__ int   g_cur   [NN];
__device__ int   g_col   [EE];
__device__ float g_dis   [NN];
__device__ float g_sumdis[NN];
__device__ int   g_bsum  [128];
__device__ int   g_boff  [128];
__device__ float g_stat_s[4 * 64];
__device__ float g_stat_q[4 * 64];
__device__ float g_hg    [GG * HH];
__device__ uint32_t g_Bhi[4 * 2048];
__device__ uint32_t g_Blo[4 * 2048];

static __device__ __forceinline__ void split2(float x, float y, uint32_t& hi, uint32_t& lo) {
    __nv_bfloat16 hx = __float2bfloat16(x), hy = __float2bfloat16(y);
    __nv_bfloat16 lx = __float2bfloat16(x - __bfloat162float(hx));
    __nv_bfloat16 ly = __float2bfloat16(y - __bfloat162float(hy));
    hi = (uint32_t)__bfloat16_as_ushort(hx) | ((uint32_t)__bfloat16_as_ushort(hy) << 16);
    lo = (uint32_t)__bfloat16_as_ushort(lx) | ((uint32_t)__bfloat16_as_ushort(ly) << 16);
}

#define MMA_BF16(c, a0, a1, a2, a3, b0, b1) \
    asm volatile("mma.sync.aligned.m16n8k16.row.col.f32.bf16.bf16.f32 " \
        "{%0,%1,%2,%3}, {%4,%5,%6,%7}, {%8,%9}, {%0,%1,%2,%3};" \
        : "+f"(c[0]), "+f"(c[1]), "+f"(c[2]), "+f"(c[3]) \
        : "r"(a0), "r"(a1), "r"(a2), "r"(a3), "r"(b0), "r"(b1))

// ---------------- CSR chain ----------------
__global__ void k_zero_deg() {
    int i = blockIdx.x * blockDim.x + threadIdx.x;
    if (i < NN) { g_outdeg[i] = 0; g_indeg[i] = 0; g_sumdis[i] = 0.f; }
}

__global__ void k_hist(const int* __restrict__ src, const int* __restrict__ dst) {
    int e = blockIdx.x * blockDim.x + threadIdx.x;
    if (e < EE) {
        atomicAdd(&g_indeg[dst[e]], 1);
        atomicAdd(&g_outdeg[src[e]], 1);
    }
}

// shuffle-based block scan (1024 threads, 2 barriers)
__global__ void k_scan1() {
    __shared__ int wtot[32];
    int t = threadIdx.x, lane = t & 31, w = t >> 5;
    int i = blockIdx.x * 1024 + t;
    int v = (i < NN) ? g_indeg[i] : 0;
    int x = v;
    #pragma unroll
    for (int o = 1; o < 32; o <<= 1) {
        int y = __shfl_up_sync(0xFFFFFFFFu, x, o);
        if (lane >= o) x += y;
    }
    if (lane == 31) wtot[w] = x;
    __syncthreads();
    if (w == 0) {
        int y = wtot[lane];
        #pragma unroll
        for (int o = 1; o < 32; o <<= 1) {
            int z = __shfl_up_sync(0xFFFFFFFFu, y, o);
            if (lane >= o) y += z;
        }
        wtot[lane] = y;
    }
    __syncthreads();
    int excl = x - v + (w > 0 ? wtot[w - 1] : 0);
    if (i < NN) g_rowptr[i] = excl;
    if (t == 1023) g_bsum[blockIdx.x] = wtot[31];
}

__global__ void k_scan2(int nb) {
    __shared__ int wtot[4];
    int t = threadIdx.x, lane = t & 31, w = t >> 5;
    int v = (t < nb) ? g_bsum[t] : 0;
    int x = v;
    #pragma unroll
    for (int o = 1; o < 32; o <<= 1) {
        int y = __shfl_up_sync(0xFFFFFFFFu, x, o);
        if (lane >= o) x += y;
    }
    if (lane == 31) wtot[w] = x;
    __syncthreads();
    int off = 0;
    for (int j = 0; j < w; j++) off += wtot[j];
    g_boff[t] = x - v + off;
    if (t == 127) g_rowptr[NN] = off + x;
}

__global__ void k_scan3() {
    int i = blockIdx.x * 1024 + threadIdx.x;
    if (i < NN) {
        int v = g_rowptr[i] + g_boff[blockIdx.x];
        g_rowptr[i] = v;
        g_cur[i] = v;
        g_dis[i] = rsqrtf((float)g_outdeg[i] + 1.0f);
    }
}

__global__ void k_fill(const int* __restrict__ src, const int* __restrict__ dst) {
    int e = blockIdx.x * blockDim.x + threadIdx.x;
    if (e < EE) {
        int s = src[e];
        int d = dst[e];
        int p = atomicAdd(&g_cur[d], 1);
        g_col[p] = s;
        atomicAdd(&g_sumdis[d], g_dis[s]);
    }
}

// ---------------- feature chain setup: zero stats/hg + pre-split weights (merged) ----------------
__global__ void k_prep(const float* __restrict__ Wf, const float* __restrict__ Wc) {
    int t = blockIdx.x * blockDim.x + threadIdx.x;   // grid 33*256 = 8448
    if (t < 256) { g_stat_s[t] = 0.f; g_stat_q[t] = 0.f; }
    if (t < GG * HH) g_hg[t] = 0.f;
    if (t < 8192) {
        int L = t >> 11, rem = t & 2047;
        int n = rem >> 5, kp = rem & 31;
        const float* W = (L == 0) ? Wf : (Wc + (L - 1) * 4096);
        float w0 = W[(2 * kp) * 64 + n];
        float w1 = W[(2 * kp + 1) * 64 + n];
        uint32_t hi, lo;
        split2(w0, w1, hi, lo);
        g_Bhi[L * 2048 + rem] = hi;
        g_Blo[L * 2048 + rem] = lo;
    }
}

__global__ void k_colstats(const float* __restrict__ A) {
    __shared__ float rs[256], rq[256];
    int c  = threadIdx.x & 63;
    int rr = threadIdx.x >> 6;
    int rbeg = blockIdx.x * 512;
    int rend = rbeg + 512; if (rend > NN) rend = NN;
    float s = 0.f, q = 0.f;
    for (int r = rbeg + rr; r < rend; r += 4) {
        float v = A[(size_t)r * 64 + c];
        s += v; q += v * v;
    }
    rs[threadIdx.x] = s; rq[threadIdx.x] = q;
    __syncthreads();
    if (threadIdx.x < 64) {
        float S = rs[threadIdx.x] + rs[threadIdx.x + 64] + rs[threadIdx.x + 128] + rs[threadIdx.x + 192];
        float Q = rq[threadIdx.x] + rq[threadIdx.x + 64] + rq[threadIdx.x + 128] + rq[threadIdx.x + 192];
        atomicAdd(&g_stat_s[threadIdx.x], S);
        atomicAdd(&g_stat_q[threadIdx.x], Q);
    }
}

// ---------------- mma.sync GEMM: relu(A'@W+bias); stores dis-scaled h; fused stats/pool ----------------
// aBf16=0: stage A from fp32 Ain (optional BN fold). aBf16=1: stage from g_awh/g_awl (pure copy).
__global__ __launch_bounds__(256)
void k_gemm_mma(const float* __restrict__ A, int layer,
                const float* __restrict__ bias, float* __restrict__ out,
                int statSlot, int foldSlot, int poolMode, int aBf16,
                const int* __restrict__ batch,
                const float* __restrict__ gam, const float* __restrict__ bet) {
    extern __shared__ __align__(16) char sm[];
    float*    s_s = (float*)sm;
    float*    s_t = (float*)(sm + 256);
    uint32_t* BH  = (uint32_t*)(sm + 512);
    uint32_t* BL  = (uint32_t*)(sm + 9728);
    uint32_t* AH  = (uint32_t*)(sm + 18944);
    uint32_t* AL  = (uint32_t*)(sm + 37376);
    int tid = threadIdx.x;
    int rowBase = blockIdx.x * 128;

    if (foldSlot >= 0 && tid < 64) {
        float invn = 1.0f / (float)NN;
        float mu  = g_stat_s[foldSlot * 64 + tid] * invn;
        float var = fmaxf(g_stat_q[foldSlot * 64 + tid] * invn - mu * mu, 0.f);
        float sc = rsqrtf(var + EPSBN) * gam[tid];
        s_s[tid] = sc;
        s_t[tid] = bet[tid] - mu * sc;
    }

    {
        const uint32_t* gBH = g_Bhi + layer * 2048;
        const uint32_t* gBL = g_Blo + layer * 2048;
        for (int i = tid; i < 2048; i += 256) {
            int n = i >> 5, kp = i & 31;
            BH[n * 36 + kp] = gBH[i];
            BL[n * 36 + kp] = gBL[i];
        }
    }
    __syncthreads();

    {
        int row = tid >> 1, half = tid & 1;
        int grow = rowBase + row;
        bool valid = grow < NN;
        uint32_t base = row * 36 + half * 16;
        if (aBf16) {
            if (valid) {
                const uint4* ph4 = (const uint4*)(g_awh + (size_t)grow * 32 + half * 16);
                const uint4* pl4 = (const uint4*)(g_awl + (size_t)grow * 32 + half * 16);
                uint4 h0 = ph4[0], h1 = ph4[1], h2 = ph4[2], h3 = ph4[3];
                uint4 l0 = pl4[0], l1 = pl4[1], l2 = pl4[2], l3 = pl4[3];
                *(uint4*)(AH + base)      = h0;
                *(uint4*)(AH + base + 4)  = h1;
                *(uint4*)(AH + base + 8)  = h2;
                *(uint4*)(AH + base + 12) = h3;
                *(uint4*)(AL + base)      = l0;
                *(uint4*)(AL + base + 4)  = l1;
                *(uint4*)(AL + base + 8)  = l2;
                *(uint4*)(AL + base + 12) = l3;
            } else {
                #pragma unroll
                for (int j = 0; j < 4; j++) {
                    *(uint4*)(AH + base + 4 * j) = make_uint4(0, 0, 0, 0);
                    *(uint4*)(AL + base + 4 * j) = make_uint4(0, 0, 0, 0);
                }
            }
        } else {
            const float4* ap = (const float4*)(A + (size_t)grow * 64 + half * 32);
            bool dofold = (foldSlot >= 0);
            uint32_t hb[16], lb[16];
            #pragma unroll
            for (int j = 0; j < 8; j++) {
                float4 v = valid ? ap[j] : make_float4(0.f, 0.f, 0.f, 0.f);
                if (dofold) {
                    int c0 = half * 32 + j * 4;
                    v.x = v.x * s_s[c0]     + s_t[c0];
                    v.y = v.y * s_s[c0 + 1] + s_t[c0 + 1];
                    v.z = v.z * s_s[c0 + 2] + s_t[c0 + 2];
                    v.w = v.w * s_s[c0 + 3] + s_t[c0 + 3];
                }
                split2(v.x, v.y, hb[2 * j],     lb[2 * j]);
                split2(v.z, v.w, hb[2 * j + 1], lb[2 * j + 1]);
            }
            #pragma unroll
            for (int j = 0; j < 4; j++) {
                *(uint4*)(AH + base + 4 * j) = make_uint4(hb[4 * j], hb[4 * j + 1], hb[4 * j + 2], hb[4 * j + 3]);
                *(uint4*)(AL + base + 4 * j) = make_uint4(lb[4 * j], lb[4 * j + 1], lb[4 * j + 2], lb[4 * j + 3]);
            }
        }
    }
    __syncthreads();

    int lane = tid & 31, wr = tid >> 5;
    int g = lane >> 2, t = lane & 3;
    float acc[8][4];
    #pragma unroll
    for (int nf = 0; nf < 8; nf++)
        #pragma unroll
        for (int j = 0; j < 4; j++) acc[nf][j] = 0.f;

    int ar0 = (wr * 16 + g) * 36;
    int ar1 = (wr * 16 + g + 8) * 36;
    #pragma unroll
    for (int kc = 0; kc < 4; kc++) {
        int kb = kc * 8 + t;
        uint32_t ah0 = AH[ar0 + kb],     ah1 = AH[ar1 + kb];
        uint32_t ah2 = AH[ar0 + kb + 4], ah3 = AH[ar1 + kb + 4];
        uint32_t al0 = AL[ar0 + kb],     al1 = AL[ar1 + kb];
        uint32_t al2 = AL[ar0 + kb + 4], al3 = AL[ar1 + kb + 4];
        #pragma unroll
        for (int nf = 0; nf < 8; nf++) {
            int nb = (nf * 8 + g) * 36 + kb;
            uint32_t bh0 = BH[nb], bh1 = BH[nb + 4];
            uint32_t bl0 = BL[nb], bl1 = BL[nb + 4];
            MMA_BF16(acc[nf], ah0, ah1, ah2, ah3, bh0, bh1);
            MMA_BF16(acc[nf], ah0, ah1, ah2, ah3, bl0, bl1);
            MMA_BF16(acc[nf], al0, al1, al2, al3, bh0, bh1);
        }
    }
    __syncthreads();

    int* sbatch = (int*)(sm + 36352);
    if (poolMode && tid < 128) {
        int grow = rowBase + tid;
        sbatch[tid] = batch[grow < NN ? grow : NN - 1];
    }

    {
        int r0 = rowBase + wr * 16 + g, r1 = r0 + 8;
        bool v0 = r0 < NN, v1 = r1 < NN;
        float d0 = 1.f, d1 = 1.f;
        if (!poolMode) {
            if (v0) d0 = g_dis[r0];
            if (v1) d1 = g_dis[r1];
        }
        float* T = (float*)(sm + 512);
        bool needT = (statSlot >= 0) || poolMode;
        #pragma unroll
        for (int nf = 0; nf < 8; nf++) {
            int col = nf * 8 + 2 * t;
            float2 bb = *(const float2*)(bias + col);
            float2 o0, o1;
            o0.x = fmaxf(acc[nf][0] + bb.x, 0.f);
            o0.y = fmaxf(acc[nf][1] + bb.y, 0.f);
            o1.x = fmaxf(acc[nf][2] + bb.x, 0.f);
            o1.y = fmaxf(acc[nf][3] + bb.y, 0.f);
            if (!poolMode) {
                if (v0) *(float2*)(out + (size_t)r0 * 64 + col) = make_float2(o0.x * d0, o0.y * d0);
                if (v1) *(float2*)(out + (size_t)r1 * 64 + col) = make_float2(o1.x * d1, o1.y * d1);
            }
            if (needT) {
                if (!v0) { o0.x = 0.f; o0.y = 0.f; }
                if (!v1) { o1.x = 0.f; o1.y = 0.f; }
                *(float2*)(T + (wr * 16 + g) * 66 + col)     = o0;
                *(float2*)(T + (wr * 16 + g + 8) * 66 + col) = o1;
            }
        }
    }
    if (statSlot >= 0) {
        __syncthreads();
        float* T  = (float*)(sm + 512);
        float* rS = (float*)(sm + 34304);
        float* rQ = (float*)(sm + 35328);
        int c = tid & 63, q = tid >> 6;
        float S = 0.f, Q = 0.f;
        for (int r = q * 32; r < q * 32 + 32; r++) {
            float v = T[r * 66 + c];
            S += v; Q += v * v;
        }
        rS[tid] = S; rQ[tid] = Q;
        __syncthreads();
        if (tid < 64) {
            atomicAdd(&g_stat_s[statSlot * 64 + tid], rS[tid] + rS[tid + 64] + rS[tid + 128] + rS[tid + 192]);
            atomicAdd(&g_stat_q[statSlot * 64 + tid], rQ[tid] + rQ[tid + 64] + rQ[tid + 128] + rQ[tid + 192]);
        }
    }
    if (poolMode) {
        __syncthreads();
        float* T = (float*)(sm + 512);
        int c = tid & 63, q = tid >> 6;
        int r0 = q * 32;
        int cur = sbatch[r0];
        float s = 0.f;
        for (int r = 0; r < 32; r++) {
            int gid = sbatch[r0 + r];
            if (gid != cur) {
                atomicAdd(&g_hg[cur * 64 + c], s);
                s = 0.f; cur = gid;
            }
            s += T[(r0 + r) * 66 + c];
        }
        atomicAdd(&g_hg[cur * 64 + c], s);
    }
}

// ---------------- aggregation (warp per node; pre-scaled inputs; bf16-split output) ----------------
__global__ __launch_bounds__(256)
void k_agg(const float* __restrict__ Ain,
           int slot, const float* __restrict__ gam, const float* __restrict__ bet) {
    __shared__ float s_sc[64], s_sh[64];
    if (threadIdx.x < 64) {
        float invn = 1.0f / (float)NN;
        float mu  = g_stat_s[slot * 64 + threadIdx.x] * invn;
        float var = fmaxf(g_stat_q[slot * 64 + threadIdx.x] * invn - mu * mu, 0.f);
        float sc = rsqrtf(var + EPSBN) * gam[threadIdx.x];
        s_sc[threadIdx.x] = sc;
        s_sh[threadIdx.x] = bet[threadIdx.x] - mu * sc;
    }
    __syncthreads();

    int gtid = blockIdx.x * 256 + threadIdx.x;
    int i = gtid >> 5;
    int lane = gtid & 31;
    if (i >= NN) return;
    int c0 = lane * 2;
    float di = g_dis[i];
    int e = g_rowptr[i], end = g_rowptr[i + 1];
    float a0 = 0.f, a1 = 0.f;

    for (; e + 8 <= end; e += 8) {
        int s0 = g_col[e],     s1 = g_col[e + 1], s2 = g_col[e + 2], s3 = g_col[e + 3];
        int s4 = g_col[e + 4], s5 = g_col[e + 5], s6 = g_col[e + 6], s7 = g_col[e + 7];
        float2 v0 = *(const float2*)&Ain[(size_t)s0 * 64 + c0];
        float2 v1 = *(const float2*)&Ain[(size_t)s1 * 64 + c0];
        float2 v2 = *(const float2*)&Ain[(size_t)s2 * 64 + c0];
        float2 v3 = *(const float2*)&Ain[(size_t)s3 * 64 + c0];
        float2 v4 = *(const float2*)&Ain[(size_t)s4 * 64 + c0];
        float2 v5 = *(const float2*)&Ain[(size_t)s5 * 64 + c0];
        float2 v6 = *(const float2*)&Ain[(size_t)s6 * 64 + c0];
        float2 v7 = *(const float2*)&Ain[(size_t)s7 * 64 + c0];
        a0 += v0.x + v1.x + v2.x + v3.x + v4.x + v5.x + v6.x + v7.x;
        a1 += v0.y + v1.y + v2.y + v3.y + v4.y + v5.y + v6.y + v7.y;
    }
    for (; e + 4 <= end; e += 4) {
        int s0 = g_col[e], s1 = g_col[e + 1], s2 = g_col[e + 2], s3 = g_col[e + 3];
        float2 v0 = *(const float2*)&Ain[(size_t)s0 * 64 + c0];
        float2 v1 = *(const float2*)&Ain[(size_t)s1 * 64 + c0];
        float2 v2 = *(const float2*)&Ain[(size_t)s2 * 64 + c0];
        float2 v3 = *(const float2*)&Ain[(size_t)s3 * 64 + c0];
        a0 += v0.x + v1.x + v2.x + v3.x;
        a1 += v0.y + v1.y + v2.y + v3.y;
    }
    for (; e < end; e++) {
        int s = g_col[e];
        float2 v = *(const float2*)&Ain[(size_t)s * 64 + c0];
        a0 += v.x;
        a1 += v.y;
    }
    {   // self loop
        float2 v = *(const float2*)&Ain[(size_t)i * 64 + c0];
        a0 += v.x;
        a1 += v.y;
    }
    float ws = di * (g_sumdis[i] + di);
    float o0 = s_sc[c0]     * (di * a0) + ws * s_sh[c0];
    float o1 = s_sc[c0 + 1] * (di * a1) + ws * s_sh[c0 + 1];
    uint32_t hi, lo;
    split2(o0, o1, hi, lo);
    g_awh[(size_t)i * 32 + lane] = hi;
    g_awl[(size_t)i * 32 + lane] = lo;
}

// ---------------- final head ----------------
__global__ __launch_bounds__(256, 1)
void k_final(const float* __restrict__ bn1g, const float* __restrict__ bn1b,
             const float* __restrict__ Wfc,  const float* __restrict__ bfc,
             const float* __restrict__ bn2g, const float* __restrict__ bn2b,
             const float* __restrict__ Wcls, const float* __restrict__ bcls,
             float* __restrict__ out) {
    __shared__ float sA[128 * 65];
    __shared__ float red[256], red2[256];
    __shared__ float s_s[64], s_t[64];
    int tid = threadIdx.x;
    int c = tid & 63, rr = tid >> 6;

    for (int i = tid; i < 128 * 64; i += 256)
        sA[(i >> 6) * 65 + (i & 63)] = g_hg[i];
    __syncthreads();

    float s = 0.f, q = 0.f;
    for (int r = rr; r < 128; r += 4) {
        float v = sA[r * 65 + c];
        s += v; q += v * v;
    }
    red[tid] = s; red2[tid] = q;
    __syncthreads();
    if (tid < 64) {
        float S = red [tid] + red [tid + 64] + red [tid + 128] + red [tid + 192];
        float Q = red2[tid] + red2[tid + 64] + red2[tid + 128] + red2[tid + 192];
        float mu = S * (1.f / 128.f);
        float var = fmaxf(Q * (1.f / 128.f) - mu * mu, 0.f);
        float inv = rsqrtf(var + EPSBN);
        float sc = inv * bn1g[tid];
        s_s[tid] = sc;
        s_t[tid] = bn1b[tid] - mu * sc;
    }
    __syncthreads();
    for (int r = rr; r < 128; r += 4)
        sA[r * 65 + c] = sA[r * 65 + c] * s_s[c] + s_t[c];
    __syncthreads();

    float wreg[64];
    #pragma unroll
    for (int k = 0; k < 64; k++) wreg[k] = Wfc[k * 64 + c];
    float acc[32];
    for (int ri = 0; ri < 32; ri++) {
        int r = rr + ri * 4;
        float a = bfc[c];
        #pragma unroll
        for (int k = 0; k < 64; k++) a = fmaf(sA[r * 65 + k], wreg[k], a);
        acc[ri] = fmaxf(a, 0.f);
    }
    __syncthreads();
    for (int ri = 0; ri < 32; ri++) sA[(rr + ri * 4) * 65 + c] = acc[ri];
    __syncthreads();

    s = 0.f; q = 0.f;
    for (int r = rr; r < 128; r += 4) {
        float v = sA[r * 65 + c];
        s += v; q += v * v;
    }
    red[tid] = s; red2[tid] = q;
    __syncthreads();
    if (tid < 64) {
        float S = red [tid] + red [tid + 64] + red [tid + 128] + red [tid + 192];
        float Q = red2[tid] + red2[tid + 64] + red2[tid + 128] + red2[tid + 192];
        float mu = S * (1.f / 128.f);
        float var = fmaxf(Q * (1.f / 128.f) - mu * mu, 0.f);
        float inv = rsqrtf(var + EPSBN);
        float sc = inv * bn2g[tid];
        s_s[tid] = sc;
        s_t[tid] = bn2b[tid] - mu * sc;
    }
    __syncthreads();

    if (tid < 128) {
        int r = tid;
        float logits[10];
        #pragma unroll
        for (int j = 0; j < 10; j++) logits[j] = bcls[j];
        for (int k = 0; k < 64; k++) {
            float v = sA[r * 65 + k] * s_s[k] + s_t[k];
            #pragma unroll
            for (int j = 0; j < 10; j++)
                logits[j] = fmaf(v, Wcls[k * 10 + j], logits[j]);
        }
        float m = logits[0];
        #pragma unroll
        for (int j = 1; j < 10; j++) m = fmaxf(m, logits[j]);
        float se = 0.f;
        #pragma unroll
        for (int j = 0; j < 10; j++) se += expf(logits[j] - m);
        float lse = logf(se) + m;
        #pragma unroll
        for (int j = 0; j < 10; j++) out[r * 10 + j] = logits[j] - lse;
    }
}

// ---------------- host launch ----------------
extern "C" void kernel_launch(void* const* d_in, const int* in_sizes, int n_in,
                              void* d_out, int out_size) {
    const float* x         = (const float*)d_in[0];
    const int*   ei        = (const int*)  d_in[1];
    const int*   batch     = (const int*)  d_in[2];
    const float* bn_feat_g = (const float*)d_in[3];
    const float* bn_feat_b = (const float*)d_in[4];
    const float* W_feat    = (const float*)d_in[5];
    const float* b_feat    = (const float*)d_in[6];
    const float* conv_bn_g = (const float*)d_in[7];
    const float* conv_bn_b = (const float*)d_in[8];
    const float* conv_W    = (const float*)d_in[9];
    const float* conv_b    = (const float*)d_in[10];
    const float* bn_fc_g   = (const float*)d_in[11];
    const float* bn_fc_b   = (const float*)d_in[12];
    const float* W_fc      = (const float*)d_in[13];
    const float* b_fc      = (const float*)d_in[14];
    const float* bn_hid_g  = (const float*)d_in[15];
    const float* bn_hid_b  = (const float*)d_in[16];
    const float* W_cls     = (const float*)d_in[17];
    const float* b_cls     = (const float*)d_in[18];
    float* out = (float*)d_out;

    void *ph_v;
    cudaGetSymbolAddress(&ph_v, g_h);
    float* ph = (float*)ph_v;

    const int* src = ei;
    const int* dst = ei + EE;

    const int nbScan = (NN + 1023) / 1024;
    const int nbNode = (NN + 255) / 256;
    const int nbEdge = (EE + 255) / 256;
    const int nbStat = (NN + 511) / 512;
    const int nbGemm = (NN + 127) / 128;
    const int nbAgg  = (NN * 32 + 255) / 256;
    const int MMA_SMEM = 55808;

    static cudaStream_t s_csr = 0;
    static cudaEvent_t  ev_fork = 0, ev_dis = 0, ev_join = 0;
    static bool inited = false;
    if (!inited) {
        cudaStreamCreateWithFlags(&s_csr, cudaStreamNonBlocking);
        cudaEventCreateWithFlags(&ev_fork, cudaEventDisableTiming);
        cudaEventCreateWithFlags(&ev_dis,  cudaEventDisableTiming);
        cudaEventCreateWithFlags(&ev_join, cudaEventDisableTiming);
        cudaFuncSetAttribute(k_gemm_mma, cudaFuncAttributeMaxDynamicSharedMemorySize, MMA_SMEM);
        inited = true;
    }

    // ---- fork: CSR chain on s_csr, feature chain on stream 0 ----
    cudaEventRecord(ev_fork, 0);
    cudaStreamWaitEvent(s_csr, ev_fork, 0);

    k_zero_deg<<<nbNode, 256, 0, s_csr>>>();
    k_hist<<<nbEdge, 256, 0, s_csr>>>(src, dst);
    k_scan1<<<nbScan, 1024, 0, s_csr>>>();
    k_scan2<<<1, 128, 0, s_csr>>>(nbScan);
    k_scan3<<<nbScan, 1024, 0, s_csr>>>();
    cudaEventRecord(ev_dis, s_csr);
    k_fill<<<nbEdge, 256, 0, s_csr>>>(src, dst);
    cudaEventRecord(ev_join, s_csr);

    // feature chain (stream 0)
    k_prep<<<33, 256>>>(W_feat, conv_W);
    k_colstats<<<nbStat, 256>>>(x);
    cudaStreamWaitEvent(0, ev_dis, 0);
    k_gemm_mma<<<nbGemm, 256, MMA_SMEM>>>(x, 0, b_feat, ph, 1, 0, 0, 0,
                                          batch, bn_feat_g, bn_feat_b);

    // ---- join before first aggregation ----
    cudaStreamWaitEvent(0, ev_join, 0);

    // ---- conv layers; GEMM A-tiles come pre-split from agg; last GEMM pools ----
    for (int l = 0; l < LL; l++) {
        k_agg<<<nbAgg, 256>>>(ph, l + 1, conv_bn_g + l * HH, conv_bn_b + l * HH);
        int statSlot = (l < LL - 1) ? (l + 2) : -1;
        int poolMode = (l == LL - 1) ? 1 : 0;
        k_gemm_mma<<<nbGemm, 256, MMA_SMEM>>>((const float*)0, l + 1, conv_b + l * HH, ph,
                                              statSlot, -1, poolMode, 1,
                                              batch, (const float*)0, (const float*)0);
    }

    // ---- head ----
    k_final<<<1, 256>>>(bn_fc_g, bn_fc_b, W_fc, b_fc,
                        bn_hid_g, bn_hid_b, W_cls, b_cls, out);
}

// round 17
// speedup vs baseline: 1.1154x; 1.0110x over previous
#include <cuda_runtime.h>
#include <cuda_bf16.h>
#include <cuda_fp16.h>
#include <math.h>
#include <stdint.h>

#define NN 100000
#define EE 1200000
#define CC 64
#define HH 64
#define OUTC 10
#define GG 128
#define LL 3
#define EPSBN 1e-5f
#define NBSTAT 196   // (NN+511)/512

// ---------------- scratch (device globals; zero-initialized at load, self-restored by k_final) ----------------
__device__ __half   g_h [NN * HH];    // scaled features  hhat = dis * h  (fp16)
__device__ uint32_t g_awh[NN * 32];   // agg output, bf16x2 hi
__device__ uint32_t g_awl[NN * 32];   // agg output, bf16x2 lo
__device__ int   g_outdeg[NN];
__device__ int   g_indeg [NN];
__device__ int   g_rowptr[NN + 1];
__device__ int   g_cur   [NN];
__device__ int   g_col   [EE];
__device__ float g_dis   [NN];
__device__ float g_sumdis[NN];
__device__ int   g_bsum  [128];
__device__ float g_stat_s[4 * 64];
__device__ float g_stat_q[4 * 64];
__device__ float g_hg    [GG * HH];
__device__ uint32_t g_Bhi[4 * 2048];
__device__ uint32_t g_Blo[4 * 2048];

static __device__ __forceinline__ void split2(float x, float y, uint32_t& hi, uint32_t& lo) {
    __nv_bfloat16 hx = __float2bfloat16(x), hy = __float2bfloat16(y);
    __nv_bfloat16 lx = __float2bfloat16(x - __bfloat162float(hx));
    __nv_bfloat16 ly = __float2bfloat16(y - __bfloat162float(hy));
    hi = (uint32_t)__bfloat16_as_ushort(hx) | ((uint32_t)__bfloat16_as_ushort(hy) << 16);
    lo = (uint32_t)__bfloat16_as_ushort(lx) | ((uint32_t)__bfloat16_as_ushort(ly) << 16);
}

#define MMA_BF16(c, a0, a1, a2, a3, b0, b1) \
    asm volatile("mma.sync.aligned.m16n8k16.row.col.f32.bf16.bf16.f32 " \
        "{%0,%1,%2,%3}, {%4,%5,%6,%7}, {%8,%9}, {%0,%1,%2,%3};" \
        : "+f"(c[0]), "+f"(c[1]), "+f"(c[2]), "+f"(c[3]) \
        : "r"(a0), "r"(a1), "r"(a2), "r"(a3), "r"(b0), "r"(b1))

// ---------------- CSR chain ----------------
__global__ void k_zero_deg() {
    int i = blockIdx.x * blockDim.x + threadIdx.x;
    if (i < NN) { g_outdeg[i] = 0; g_indeg[i] = 0; g_sumdis[i] = 0.f; }
}

__global__ void k_hist(const int* __restrict__ src, const int* __restrict__ dst) {
    int e = blockIdx.x * blockDim.x + threadIdx.x;
    if (e < EE) {
        atomicAdd(&g_indeg[dst[e]], 1);
        atomicAdd(&g_outdeg[src[e]], 1);
    }
}

// shuffle-based block scan (1024 threads, 2 barriers)
__global__ void k_scan1() {
    __shared__ int wtot[32];
    int t = threadIdx.x, lane = t & 31, w = t >> 5;
    int i = blockIdx.x * 1024 + t;
    int v = (i < NN) ? g_indeg[i] : 0;
    int x = v;
    #pragma unroll
    for (int o = 1; o < 32; o <<= 1) {
        int y = __shfl_up_sync(0xFFFFFFFFu, x, o);
        if (lane >= o) x += y;
    }
    if (lane == 31) wtot[w] = x;
    __syncthreads();
    if (w == 0) {
        int y = wtot[lane];
        #pragma unroll
        for (int o = 1; o < 32; o <<= 1) {
            int z = __shfl_up_sync(0xFFFFFFFFu, y, o);
            if (lane >= o) y += z;
        }
        wtot[lane] = y;
    }
    __syncthreads();
    int excl = x - v + (w > 0 ? wtot[w - 1] : 0);
    if (i < NN) g_rowptr[i] = excl;
    if (t == 1023) g_bsum[blockIdx.x] = wtot[31];
}

// scan3 with inlined block-sum scan (scan2 folded in; each block redoes the tiny scan)
__global__ void k_scan3(int nb) {
    __shared__ int sboff[128];
    __shared__ int wt[4];
    __shared__ int stot;
    int t = threadIdx.x;
    int lane = t & 31, w = t >> 5;
    int v = 0, x = 0;
    if (t < 128) {
        v = (t < nb) ? g_bsum[t] : 0;
        x = v;
        #pragma unroll
        for (int o = 1; o < 32; o <<= 1) {
            int y = __shfl_up_sync(0xFFFFFFFFu, x, o);
            if (lane >= o) x += y;
        }
        if (lane == 31) wt[w] = x;
    }
    __syncthreads();
    if (t < 128) {
        int off = 0;
        for (int j = 0; j < w; j++) off += wt[j];
        sboff[t] = x - v + off;
        if (t == 0) stot = wt[0] + wt[1] + wt[2] + wt[3];
    }
    __syncthreads();
    int i = blockIdx.x * 1024 + t;
    if (i < NN) {
        int val = g_rowptr[i] + sboff[blockIdx.x];
        g_rowptr[i] = val;
        g_cur[i] = val;
        g_dis[i] = rsqrtf((float)g_outdeg[i] + 1.0f);
    }
    if (blockIdx.x == 0 && t == 0) g_rowptr[NN] = stot;
}

__global__ void k_fill(const int* __restrict__ src, const int* __restrict__ dst) {
    int e = blockIdx.x * blockDim.x + threadIdx.x;
    if (e < EE) {
        int s = src[e];
        int d = dst[e];
        int p = atomicAdd(&g_cur[d], 1);
        g_col[p] = s;
        atomicAdd(&g_sumdis[d], g_dis[s]);
    }
}

// ---------------- colstats(x) + weight pre-split, merged (stats pre-zeroed by k_final/init) ----------------
__global__ void k_colstats_prep(const float* __restrict__ A,
                                const float* __restrict__ Wf, const float* __restrict__ Wc) {
    if (blockIdx.x < NBSTAT) {
        __shared__ float rs[256], rq[256];
        int c  = threadIdx.x & 63;
        int rr = threadIdx.x >> 6;
        int rbeg = blockIdx.x * 512;
        int rend = rbeg + 512; if (rend > NN) rend = NN;
        float s = 0.f, q = 0.f;
        for (int r = rbeg + rr; r < rend; r += 4) {
            float v = A[(size_t)r * 64 + c];
            s += v; q += v * v;
        }
        rs[threadIdx.x] = s; rq[threadIdx.x] = q;
        __syncthreads();
        if (threadIdx.x < 64) {
            float S = rs[threadIdx.x] + rs[threadIdx.x + 64] + rs[threadIdx.x + 128] + rs[threadIdx.x + 192];
            float Q = rq[threadIdx.x] + rq[threadIdx.x + 64] + rq[threadIdx.x + 128] + rq[threadIdx.x + 192];
            atomicAdd(&g_stat_s[threadIdx.x], S);
            atomicAdd(&g_stat_q[threadIdx.x], Q);
        }
    } else {
        int t = (blockIdx.x - NBSTAT) * 256 + threadIdx.x;
        if (t < 8192) {
            int L = t >> 11, rem = t & 2047;
            int n = rem >> 5, kp = rem & 31;
            const float* W = (L == 0) ? Wf : (Wc + (L - 1) * 4096);
            float w0 = W[(2 * kp) * 64 + n];
            float w1 = W[(2 * kp + 1) * 64 + n];
            uint32_t hi, lo;
            split2(w0, w1, hi, lo);
            g_Bhi[L * 2048 + rem] = hi;
            g_Blo[L * 2048 + rem] = lo;
        }
    }
}

// ---------------- mma.sync GEMM: relu(A'@W+bias); stores dis-scaled fp16 h; fused stats/pool ----------------
__global__ __launch_bounds__(256)
void k_gemm_mma(const float* __restrict__ A, int layer,
                const float* __restrict__ bias, __half* __restrict__ out,
                int statSlot, int foldSlot, int poolMode, int aBf16,
                const int* __restrict__ batch,
                const float* __restrict__ gam, const float* __restrict__ bet) {
    extern __shared__ __align__(16) char sm[];
    float*    s_s = (float*)sm;
    float*    s_t = (float*)(sm + 256);
    uint32_t* BH  = (uint32_t*)(sm + 512);
    uint32_t* BL  = (uint32_t*)(sm + 9728);
    uint32_t* AH  = (uint32_t*)(sm + 18944);
    uint32_t* AL  = (uint32_t*)(sm + 37376);
    int tid = threadIdx.x;
    int rowBase = blockIdx.x * 128;

    if (foldSlot >= 0 && tid < 64) {
        float invn = 1.0f / (float)NN;
        float mu  = g_stat_s[foldSlot * 64 + tid] * invn;
        float var = fmaxf(g_stat_q[foldSlot * 64 + tid] * invn - mu * mu, 0.f);
        float sc = rsqrtf(var + EPSBN) * gam[tid];
        s_s[tid] = sc;
        s_t[tid] = bet[tid] - mu * sc;
    }

    {
        const uint32_t* gBH = g_Bhi + layer * 2048;
        const uint32_t* gBL = g_Blo + layer * 2048;
        for (int i = tid; i < 2048; i += 256) {
            int n = i >> 5, kp = i & 31;
            BH[n * 36 + kp] = gBH[i];
            BL[n * 36 + kp] = gBL[i];
        }
    }
    __syncthreads();

    {
        int row = tid >> 1, half = tid & 1;
        int grow = rowBase + row;
        bool valid = grow < NN;
        uint32_t base = row * 36 + half * 16;
        if (aBf16) {
            if (valid) {
                const uint4* ph4 = (const uint4*)(g_awh + (size_t)grow * 32 + half * 16);
                const uint4* pl4 = (const uint4*)(g_awl + (size_t)grow * 32 + half * 16);
                uint4 h0 = ph4[0], h1 = ph4[1], h2 = ph4[2], h3 = ph4[3];
                uint4 l0 = pl4[0], l1 = pl4[1], l2 = pl4[2], l3 = pl4[3];
                *(uint4*)(AH + base)      = h0;
                *(uint4*)(AH + base + 4)  = h1;
                *(uint4*)(AH + base + 8)  = h2;
                *(uint4*)(AH + base + 12) = h3;
                *(uint4*)(AL + base)      = l0;
                *(uint4*)(AL + base + 4)  = l1;
                *(uint4*)(AL + base + 8)  = l2;
                *(uint4*)(AL + base + 12) = l3;
            } else {
                #pragma unroll
                for (int j = 0; j < 4; j++) {
                    *(uint4*)(AH + base + 4 * j) = make_uint4(0, 0, 0, 0);
                    *(uint4*)(AL + base + 4 * j) = make_uint4(0, 0, 0, 0);
                }
            }
        } else {
            const float4* ap = (const float4*)(A + (size_t)grow * 64 + half * 32);
            bool dofold = (foldSlot >= 0);
            uint32_t hb[16], lb[16];
            #pragma unroll
            for (int j = 0; j < 8; j++) {
                float4 v = valid ? ap[j] : make_float4(0.f, 0.f, 0.f, 0.f);
                if (dofold) {
                    int c0 = half * 32 + j * 4;
                    v.x = v.x * s_s[c0]     + s_t[c0];
                    v.y = v.y * s_s[c0 + 1] + s_t[c0 + 1];
                    v.z = v.z * s_s[c0 + 2] + s_t[c0 + 2];
                    v.w = v.w * s_s[c0 + 3] + s_t[c0 + 3];
                }
                split2(v.x, v.y, hb[2 * j],     lb[2 * j]);
                split2(v.z, v.w, hb[2 * j + 1], lb[2 * j + 1]);
            }
            #pragma unroll
            for (int j = 0; j < 4; j++) {
                *(uint4*)(AH + base + 4 * j) = make_uint4(hb[4 * j], hb[4 * j + 1], hb[4 * j + 2], hb[4 * j + 3]);
                *(uint4*)(AL + base + 4 * j) = make_uint4(lb[4 * j], lb[4 * j + 1], lb[4 * j + 2], lb[4 * j + 3]);
            }
        }
    }
    __syncthreads();

    int lane = tid & 31, wr = tid >> 5;
    int g = lane >> 2, t = lane & 3;
    float acc[8][4];
    #pragma unroll
    for (int nf = 0; nf < 8; nf++)
        #pragma unroll
        for (int j = 0; j < 4; j++) acc[nf][j] = 0.f;

    int ar0 = (wr * 16 + g) * 36;
    int ar1 = (wr * 16 + g + 8) * 36;
    #pragma unroll
    for (int kc = 0; kc < 4; kc++) {
        int kb = kc * 8 + t;
        uint32_t ah0 = AH[ar0 + kb],     ah1 = AH[ar1 + kb];
        uint32_t ah2 = AH[ar0 + kb + 4], ah3 = AH[ar1 + kb + 4];
        uint32_t al0 = AL[ar0 + kb],     al1 = AL[ar1 + kb];
        uint32_t al2 = AL[ar0 + kb + 4], al3 = AL[ar1 + kb + 4];
        #pragma unroll
        for (int nf = 0; nf < 8; nf++) {
            int nb = (nf * 8 + g) * 36 + kb;
            uint32_t bh0 = BH[nb], bh1 = BH[nb + 4];
            uint32_t bl0 = BL[nb], bl1 = BL[nb + 4];
            MMA_BF16(acc[nf], ah0, ah1, ah2, ah3, bh0, bh1);
            MMA_BF16(acc[nf], ah0, ah1, ah2, ah3, bl0, bl1);
            MMA_BF16(acc[nf], al0, al1, al2, al3, bh0, bh1);
        }
    }
    __syncthreads();

    int* sbatch = (int*)(sm + 36352);
    if (poolMode && tid < 128) {
        int grow = rowBase + tid;
        sbatch[tid] = batch[grow < NN ? grow : NN - 1];
    }

    {
        int r0 = rowBase + wr * 16 + g, r1 = r0 + 8;
        bool v0 = r0 < NN, v1 = r1 < NN;
        float d0 = 1.f, d1 = 1.f;
        if (!poolMode) {
            if (v0) d0 = g_dis[r0];
            if (v1) d1 = g_dis[r1];
        }
        float* T = (float*)(sm + 512);
        bool needT = (statSlot >= 0) || poolMode;
        #pragma unroll
        for (int nf = 0; nf < 8; nf++) {
            int col = nf * 8 + 2 * t;
            float2 bb = *(const float2*)(bias + col);
            float2 o0, o1;
            o0.x = fmaxf(acc[nf][0] + bb.x, 0.f);
            o0.y = fmaxf(acc[nf][1] + bb.y, 0.f);
            o1.x = fmaxf(acc[nf][2] + bb.x, 0.f);
            o1.y = fmaxf(acc[nf][3] + bb.y, 0.f);
            if (!poolMode) {
                if (v0) *(__half2*)(out + (size_t)r0 * 64 + col) = __floats2half2_rn(o0.x * d0, o0.y * d0);
                if (v1) *(__half2*)(out + (size_t)r1 * 64 + col) = __floats2half2_rn(o1.x * d1, o1.y * d1);
            }
            if (needT) {
                if (!v0) { o0.x = 0.f; o0.y = 0.f; }
                if (!v1) { o1.x = 0.f; o1.y = 0.f; }
                *(float2*)(T + (wr * 16 + g) * 66 + col)     = o0;
                *(float2*)(T + (wr * 16 + g + 8) * 66 + col) = o1;
            }
        }
    }
    if (statSlot >= 0) {
        __syncthreads();
        float* T  = (float*)(sm + 512);
        float* rS = (float*)(sm + 34304);
        float* rQ = (float*)(sm + 35328);
        int c = tid & 63, q = tid >> 6;
        float S = 0.f, Q = 0.f;
        for (int r = q * 32; r < q * 32 + 32; r++) {
            float v = T[r * 66 + c];
            S += v; Q += v * v;
        }
        rS[tid] = S; rQ[tid] = Q;
        __syncthreads();
        if (tid < 64) {
            atomicAdd(&g_stat_s[statSlot * 64 + tid], rS[tid] + rS[tid + 64] + rS[tid + 128] + rS[tid + 192]);
            atomicAdd(&g_stat_q[statSlot * 64 + tid], rQ[tid] + rQ[tid + 64] + rQ[tid + 128] + rQ[tid + 192]);
        }
    }
    if (poolMode) {
        __syncthreads();
        float* T = (float*)(sm + 512);
        int c = tid & 63, q = tid >> 6;
        int r0 = q * 32;
        int cur = sbatch[r0];
        float s = 0.f;
        for (int r = 0; r < 32; r++) {
            int gid = sbatch[r0 + r];
            if (gid != cur) {
                atomicAdd(&g_hg[cur * 64 + c], s);
                s = 0.f; cur = gid;
            }
            s += T[(r0 + r) * 66 + c];
        }
        atomicAdd(&g_hg[cur * 64 + c], s);
    }
}

// ---------------- aggregation (warp per node; fp16 gathers; bf16-split output) ----------------
__global__ __launch_bounds__(256)
void k_agg(const __half* __restrict__ Ain,
           int slot, const float* __restrict__ gam, const float* __restrict__ bet) {
    __shared__ float s_sc[64], s_sh[64];
    if (threadIdx.x < 64) {
        float invn = 1.0f / (float)NN;
        float mu  = g_stat_s[slot * 64 + threadIdx.x] * invn;
        float var = fmaxf(g_stat_q[slot * 64 + threadIdx.x] * invn - mu * mu, 0.f);
        float sc = rsqrtf(var + EPSBN) * gam[threadIdx.x];
        s_sc[threadIdx.x] = sc;
        s_sh[threadIdx.x] = bet[threadIdx.x] - mu * sc;
    }
    __syncthreads();

    int gtid = blockIdx.x * 256 + threadIdx.x;
    int i = gtid >> 5;
    int lane = gtid & 31;
    if (i >= NN) return;
    int c0 = lane * 2;
    const __half2* hp = (const __half2*)Ain;   // row s at hp[s*32 + lane]
    float di = g_dis[i];
    int e = g_rowptr[i], end = g_rowptr[i + 1];
    float a0 = 0.f, a1 = 0.f;

    for (; e + 8 <= end; e += 8) {
        int s0 = g_col[e],     s1 = g_col[e + 1], s2 = g_col[e + 2], s3 = g_col[e + 3];
        int s4 = g_col[e + 4], s5 = g_col[e + 5], s6 = g_col[e + 6], s7 = g_col[e + 7];
        float2 v0 = __half22float2(hp[(size_t)s0 * 32 + lane]);
        float2 v1 = __half22float2(hp[(size_t)s1 * 32 + lane]);
        float2 v2 = __half22float2(hp[(size_t)s2 * 32 + lane]);
        float2 v3 = __half22float2(hp[(size_t)s3 * 32 + lane]);
        float2 v4 = __half22float2(hp[(size_t)s4 * 32 + lane]);
        float2 v5 = __half22float2(hp[(size_t)s5 * 32 + lane]);
        float2 v6 = __half22float2(hp[(size_t)s6 * 32 + lane]);
        float2 v7 = __half22float2(hp[(size_t)s7 * 32 + lane]);
        a0 += v0.x + v1.x + v2.x + v3.x + v4.x + v5.x + v6.x + v7.x;
        a1 += v0.y + v1.y + v2.y + v3.y + v4.y + v5.y + v6.y + v7.y;
    }
    for (; e + 4 <= end; e += 4) {
        int s0 = g_col[e], s1 = g_col[e + 1], s2 = g_col[e + 2], s3 = g_col[e + 3];
        float2 v0 = __half22float2(hp[(size_t)s0 * 32 + lane]);
        float2 v1 = __half22float2(hp[(size_t)s1 * 32 + lane]);
        float2 v2 = __half22float2(hp[(size_t)s2 * 32 + lane]);
        float2 v3 = __half22float2(hp[(size_t)s3 * 32 + lane]);
        a0 += v0.x + v1.x + v2.x + v3.x;
        a1 += v0.y + v1.y + v2.y + v3.y;
    }
    for (; e < end; e++) {
        int s = g_col[e];
        float2 v = __half22float2(hp[(size_t)s * 32 + lane]);
        a0 += v.x;
        a1 += v.y;
    }
    {   // self loop
        float2 v = __half22float2(hp[(size_t)i * 32 + lane]);
        a0 += v.x;
        a1 += v.y;
    }
    float ws = di * (g_sumdis[i] + di);
    float o0 = s_sc[c0]     * (di * a0) + ws * s_sh[c0];
    float o1 = s_sc[c0 + 1] * (di * a1) + ws * s_sh[c0 + 1];
    uint32_t hi, lo;
    split2(o0, o1, hi, lo);
    g_awh[(size_t)i * 32 + lane] = hi;
    g_awl[(size_t)i * 32 + lane] = lo;
}

// ---------------- final head (also restores stats/hg to zero for next replay) ----------------
__global__ __launch_bounds__(256, 1)
void k_final(const float* __restrict__ bn1g, const float* __restrict__ bn1b,
             const float* __restrict__ Wfc,  const float* __restrict__ bfc,
             const float* __restrict__ bn2g, const float* __restrict__ bn2b,
             const float* __restrict__ Wcls, const float* __restrict__ bcls,
             float* __restrict__ out) {
    __shared__ float sA[128 * 65];
    __shared__ float red[256], red2[256];
    __shared__ float s_s[64], s_t[64];
    int tid = threadIdx.x;
    int c = tid & 63, rr = tid >> 6;

    for (int i = tid; i < 128 * 64; i += 256)
        sA[(i >> 6) * 65 + (i & 63)] = g_hg[i];
    __syncthreads();

    // self-restore device state for the next graph replay
    for (int i = tid; i < GG * HH; i += 256) g_hg[i] = 0.f;
    g_stat_s[tid] = 0.f;
    g_stat_q[tid] = 0.f;

    float s = 0.f, q = 0.f;
    for (int r = rr; r < 128; r += 4) {
        float v = sA[r * 65 + c];
        s += v; q += v * v;
    }
    red[tid] = s; red2[tid] = q;
    __syncthreads();
    if (tid < 64) {
        float S = red [tid] + red [tid + 64] + red [tid + 128] + red [tid + 192];
        float Q = red2[tid] + red2[tid + 64] + red2[tid + 128] + red2[tid + 192];
        float mu = S * (1.f / 128.f);
        float var = fmaxf(Q * (1.f / 128.f) - mu * mu, 0.f);
        float inv = rsqrtf(var + EPSBN);
        float sc = inv * bn1g[tid];
        s_s[tid] = sc;
        s_t[tid] = bn1b[tid] - mu * sc;
    }
    __syncthreads();
    for (int r = rr; r < 128; r += 4)
        sA[r * 65 + c] = sA[r * 65 + c] * s_s[c] + s_t[c];
    __syncthreads();

    float wreg[64];
    #pragma unroll
    for (int k = 0; k < 64; k++) wreg[k] = Wfc[k * 64 + c];
    float acc[32];
    for (int ri = 0; ri < 32; ri++) {
        int r = rr + ri * 4;
        float a = bfc[c];
        #pragma unroll
        for (int k = 0; k < 64; k++) a = fmaf(sA[r * 65 + k], wreg[k], a);
        acc[ri] = fmaxf(a, 0.f);
    }
    __syncthreads();
    for (int ri = 0; ri < 32; ri++) sA[(rr + ri * 4) * 65 + c] = acc[ri];
    __syncthreads();

    s = 0.f; q = 0.f;
    for (int r = rr; r < 128; r += 4) {
        float v = sA[r * 65 + c];
        s += v; q += v * v;
    }
    red[tid] = s; red2[tid] = q;
    __syncthreads();
    if (tid < 64) {
        float S = red [tid] + red [tid + 64] + red [tid + 128] + red [tid + 192];
        float Q = red2[tid] + red2[tid + 64] + red2[tid + 128] + red2[tid + 192];
        float mu = S * (1.f / 128.f);
        float var = fmaxf(Q * (1.f / 128.f) - mu * mu, 0.f);
        float inv = rsqrtf(var + EPSBN);
        float sc = inv * bn2g[tid];
        s_s[tid] = sc;
        s_t[tid] = bn2b[tid] - mu * sc;
    }
    __syncthreads();

    if (tid < 128) {
        int r = tid;
        float logits[10];
        #pragma unroll
        for (int j = 0; j < 10; j++) logits[j] = bcls[j];
        for (int k = 0; k < 64; k++) {
            float v = sA[r * 65 + k] * s_s[k] + s_t[k];
            #pragma unroll
            for (int j = 0; j < 10; j++)
                logits[j] = fmaf(v, Wcls[k * 10 + j], logits[j]);
        }
        float m = logits[0];
        #pragma unroll
        for (int j = 1; j < 10; j++) m = fmaxf(m, logits[j]);
        float se = 0.f;
        #pragma unroll
        for (int j = 0; j < 10; j++) se += expf(logits[j] - m);
        float lse = logf(se) + m;
        #pragma unroll
        for (int j = 0; j < 10; j++) out[r * 10 + j] = logits[j] - lse;
    }
}

// ---------------- host launch ----------------
extern "C" void kernel_launch(void* const* d_in, const int* in_sizes, int n_in,
                              void* d_out, int out_size) {
    const float* x         = (const float*)d_in[0];
    const int*   ei        = (const int*)  d_in[1];
    const int*   batch     = (const int*)  d_in[2];
    const float* bn_feat_g = (const float*)d_in[3];
    const float* bn_feat_b = (const float*)d_in[4];
    const float* W_feat    = (const float*)d_in[5];
    const float* b_feat    = (const float*)d_in[6];
    const float* conv_bn_g = (const float*)d_in[7];
    const float* conv_bn_b = (const float*)d_in[8];
    const float* conv_W    = (const float*)d_in[9];
    const float* conv_b    = (const float*)d_in[10];
    const float* bn_fc_g   = (const float*)d_in[11];
    const float* bn_fc_b   = (const float*)d_in[12];
    const float* W_fc      = (const float*)d_in[13];
    const float* b_fc      = (const float*)d_in[14];
    const float* bn_hid_g  = (const float*)d_in[15];
    const float* bn_hid_b  = (const float*)d_in[16];
    const float* W_cls     = (const float*)d_in[17];
    const float* b_cls     = (const float*)d_in[18];
    float* out = (float*)d_out;

    void *ph_v;
    cudaGetSymbolAddress(&ph_v, g_h);
    __half* ph = (__half*)ph_v;

    const int* src = ei;
    const int* dst = ei + EE;

    const int nbScan = (NN + 1023) / 1024;
    const int nbNode = (NN + 255) / 256;
    const int nbEdge = (EE + 255) / 256;
    const int nbGemm = (NN + 127) / 128;
    const int nbAgg  = (NN * 32 + 255) / 256;
    const int MMA_SMEM = 55808;

    static cudaStream_t s_csr = 0;
    static cudaEvent_t  ev_fork = 0, ev_dis = 0, ev_join = 0;
    static bool inited = false;
    if (!inited) {
        cudaStreamCreateWithFlags(&s_csr, cudaStreamNonBlocking);
        cudaEventCreateWithFlags(&ev_fork, cudaEventDisableTiming);
        cudaEventCreateWithFlags(&ev_dis,  cudaEventDisableTiming);
        cudaEventCreateWithFlags(&ev_join, cudaEventDisableTiming);
        cudaFuncSetAttribute(k_gemm_mma, cudaFuncAttributeMaxDynamicSharedMemorySize, MMA_SMEM);
        inited = true;
    }

    // ---- fork: CSR chain on s_csr, feature chain on stream 0 ----
    cudaEventRecord(ev_fork, 0);
    cudaStreamWaitEvent(s_csr, ev_fork, 0);

    k_zero_deg<<<nbNode, 256, 0, s_csr>>>();
    k_hist<<<nbEdge, 256, 0, s_csr>>>(src, dst);
    k_scan1<<<nbScan, 1024, 0, s_csr>>>();
    k_scan3<<<nbScan, 1024, 0, s_csr>>>(nbScan);
    cudaEventRecord(ev_dis, s_csr);
    k_fill<<<nbEdge, 256, 0, s_csr>>>(src, dst);
    cudaEventRecord(ev_join, s_csr);

    // feature chain (stream 0)
    k_colstats_prep<<<NBSTAT + 32, 256>>>(x, W_feat, conv_W);
    cudaStreamWaitEvent(0, ev_dis, 0);
    k_gemm_mma<<<nbGemm, 256, MMA_SMEM>>>(x, 0, b_feat, ph, 1, 0, 0, 0,
                                          batch, bn_feat_g, bn_feat_b);

    // ---- join before first aggregation ----
    cudaStreamWaitEvent(0, ev_join, 0);

    // ---- conv layers; GEMM A-tiles come pre-split from agg; last GEMM pools ----
    for (int l = 0; l < LL; l++) {
        k_agg<<<nbAgg, 256>>>(ph, l + 1, conv_bn_g + l * HH, conv_bn_b + l * HH);
        int statSlot = (l < LL - 1) ? (l + 2) : -1;
        int poolMode = (l == LL - 1) ? 1 : 0;
        k_gemm_mma<<<nbGemm, 256, MMA_SMEM>>>((const float*)0, l + 1, conv_b + l * HH, ph,
                                              statSlot, -1, poolMode, 1,
                                              batch, (const float*)0, (const float*)0);
    }

    // ---- head ----
    k_final<<<1, 256>>>(bn_fc_g, bn_fc_b, W_fc, b_fc,
                        bn_hid_g, bn_hid_b, W_cls, b_cls, out);
}